// round 1
// baseline (speedup 1.0000x reference)
#include <cuda_runtime.h>
#include <cuda_bf16.h>

// Problem constants (fixed by the dataset)
#define MAX_N 10000
#define DIM   256
#define MAX_WPR ((MAX_N + 63) / 64)   // 157

// Scratch (device globals; no allocation allowed)
__device__ unsigned long long g_bits[(long)MAX_N * MAX_WPR]; // packed adj1, 12.56 MB
__device__ float g_y1[MAX_N];
__device__ float g_y2[MAX_N];

// ---------------------------------------------------------------------------
// Kernel 1: pack adj1 (row-major N x N, 4-byte bool words) into bitmasks.
// One warp produces one 64-bit word: two coalesced 32-lane loads + ballots.
// ---------------------------------------------------------------------------
__global__ void pack_adj_kernel(const unsigned int* __restrict__ adj,
                                int n, int wpr,
                                unsigned long long* __restrict__ bits) {
    int warp = (blockIdx.x * blockDim.x + threadIdx.x) >> 5;
    int lane = threadIdx.x & 31;
    long total = (long)n * wpr;
    if (warp >= total) return;
    int row = warp / wpr;
    int w   = warp - row * wpr;
    long base = (long)row * n + (long)w * 64;
    int c0 = w * 64 + lane;
    int c1 = c0 + 32;
    unsigned v0 = (c0 < n) ? adj[base + lane]      : 0u;
    unsigned v1 = (c1 < n) ? adj[base + 32 + lane] : 0u;
    unsigned b0 = __ballot_sync(0xFFFFFFFFu, v0 != 0u);
    unsigned b1 = __ballot_sync(0xFFFFFFFFu, v1 != 0u);
    if (lane == 0)
        bits[(long)row * wpr + w] =
            (unsigned long long)b0 | ((unsigned long long)b1 << 32);
}

// ---------------------------------------------------------------------------
// Kernel 2: per-node projections y1[n] = x[n].W1, y2[n] = x[n].W2
// One warp per node, float4 loads, shfl reduction.
// ---------------------------------------------------------------------------
__global__ void node_y_kernel(const float* __restrict__ x,
                              const float* __restrict__ W,   // [1, 3*DIM]
                              int n,
                              float* __restrict__ y1,
                              float* __restrict__ y2) {
    int warp = (blockIdx.x * blockDim.x + threadIdx.x) >> 5;
    int lane = threadIdx.x & 31;
    if (warp >= n) return;
    const float4* xr = (const float4*)(x + (long)warp * DIM);
    const float4* w1 = (const float4*)(W + DIM);
    const float4* w2 = (const float4*)(W + 2 * DIM);
    float s1 = 0.f, s2 = 0.f;
#pragma unroll
    for (int k = 0; k < 2; k++) {
        int i = lane * 2 + k;                  // 64 float4 per row
        float4 xv = xr[i];
        float4 a  = w1[i];
        float4 b  = w2[i];
        s1 += xv.x * a.x + xv.y * a.y + xv.z * a.z + xv.w * a.w;
        s2 += xv.x * b.x + xv.y * b.y + xv.z * b.z + xv.w * b.w;
    }
#pragma unroll
    for (int o = 16; o; o >>= 1) {
        s1 += __shfl_xor_sync(0xFFFFFFFFu, s1, o);
        s2 += __shfl_xor_sync(0xFFFFFFFFu, s2, o);
    }
    if (lane == 0) { y1[warp] = s1; y2[warp] = s2; }
}

// ---------------------------------------------------------------------------
// Kernel 3: per-edge output. One warp per edge.
//   out[e] = sum_d x[ti,d]*x[tj,d]*W0[d]
//          + sum_{n in cn1} y2[n]              (bitmask AND + popbit gather)
//          + cn0 corrections via y1 (only n in {ti,tj} can be in cn0)
//          + b
// ---------------------------------------------------------------------------
__global__ void edge_kernel(const float* __restrict__ x,
                            const int* __restrict__ tar,      // [2, E]
                            const float* __restrict__ W,      // [1, 3*DIM]
                            const float* __restrict__ bxs,
                            int e_cnt, int wpr,
                            const unsigned long long* __restrict__ bits,
                            const float* __restrict__ y1,
                            const float* __restrict__ y2,
                            float* __restrict__ out) {
    int warp = (blockIdx.x * blockDim.x + threadIdx.x) >> 5;
    int lane = threadIdx.x & 31;
    if (warp >= e_cnt) return;

    int ti = tar[warp];
    int tj = tar[e_cnt + warp];

    const unsigned long long* A = bits + (long)ti * wpr;
    const unsigned long long* B = bits + (long)tj * wpr;

    float s = 0.f;
    // common 1-hop neighbors: AND of bitmask rows (rows live in L2)
    for (int w = lane; w < wpr; w += 32) {
        unsigned long long m = A[w] & B[w];
        while (m) {
            int b = __ffsll((long long)m) - 1;
            m &= m - 1;
            s += y2[w * 64 + b];
        }
    }

    // xij . W0 term
    const float4* xi = (const float4*)(x + (long)ti * DIM);
    const float4* xj = (const float4*)(x + (long)tj * DIM);
    const float4* w0 = (const float4*)W;
#pragma unroll
    for (int k = 0; k < 2; k++) {
        int i = lane * 2 + k;
        float4 a  = xi[i];
        float4 b4 = xj[i];
        float4 w  = w0[i];
        s += a.x * b4.x * w.x + a.y * b4.y * w.y
           + a.z * b4.z * w.z + a.w * b4.w * w.w;
    }

#pragma unroll
    for (int o = 16; o; o >>= 1)
        s += __shfl_xor_sync(0xFFFFFFFFu, s, o);

    if (lane == 0) {
        // cn0 corrections (hop-0/1 common minus hop-1 common): only ti, tj
        auto getbit = [&](int a, int b) -> int {
            return (int)((bits[(long)a * wpr + (b >> 6)] >> (b & 63)) & 1ULL);
        };
        float s0 = 0.f;
        if (ti == tj) {
            if (!getbit(ti, ti)) s0 = y1[ti];
        } else {
            if (getbit(tj, ti) && !getbit(ti, ti)) s0 += y1[ti];
            if (getbit(ti, tj) && !getbit(tj, tj)) s0 += y1[tj];
        }
        out[warp] = s + s0 + bxs[0];
    }
}

// ---------------------------------------------------------------------------
// Launch
// Inputs (metadata order): x[N*D] f32, adj01[N*N], adj1[N*N], tar_ei[2*E] i32,
//                          Wxs[1*3D] f32, bxs[1] f32, NCN_mode i32 (==0)
// Output: [E, 1] f32
// ---------------------------------------------------------------------------
extern "C" void kernel_launch(void* const* d_in, const int* in_sizes, int n_in,
                              void* d_out, int out_size) {
    const float*        x    = (const float*)d_in[0];
    const unsigned int* adj1 = (const unsigned int*)d_in[2];  // bool stored as 4-byte words
    const int*          tar  = (const int*)d_in[3];
    const float*        Wxs  = (const float*)d_in[4];
    const float*        bxs  = (const float*)d_in[5];
    float*              out  = (float*)d_out;

    const int N = in_sizes[0] / DIM;       // 10000
    const int E = in_sizes[3] / 2;         // 8192
    const int WPR = (N + 63) / 64;         // 157

    unsigned long long* bits;
    float *y1, *y2;
    cudaGetSymbolAddress((void**)&bits, g_bits);
    cudaGetSymbolAddress((void**)&y1, g_y1);
    cudaGetSymbolAddress((void**)&y2, g_y2);

    // Kernel 1: pack adj1 -> bitmask (dominant cost: one 400 MB streaming read)
    {
        long warps = (long)N * WPR;
        int threads = 256;                  // 8 warps/block
        long blocks = (warps + 7) / 8;
        pack_adj_kernel<<<(unsigned)blocks, threads>>>(adj1, N, WPR, bits);
    }
    // Kernel 2: per-node projections (independent of kernel 1; stream-ordered)
    {
        int threads = 256;
        int blocks = (N + 7) / 8;
        node_y_kernel<<<blocks, threads>>>(x, Wxs, N, y1, y2);
    }
    // Kernel 3: per-edge output
    {
        int threads = 256;
        int blocks = (E + 7) / 8;
        edge_kernel<<<blocks, threads>>>(x, tar, Wxs, bxs, E, WPR,
                                         bits, y1, y2, out);
    }
    (void)n_in; (void)out_size;
}

// round 2
// speedup vs baseline: 1.9503x; 1.9503x over previous
#include <cuda_runtime.h>
#include <cuda_bf16.h>

// Problem constants (fixed by the dataset)
#define MAX_N 10000
#define DIM   256
// groups of 128 columns, 4 x uint32 per group
#define MAX_GRP ((MAX_N + 127) / 128)        // 79
#define MAX_WPG (MAX_GRP * 4)                // 316 uint32 words per row

// Scratch (device globals; no allocation allowed)
__device__ unsigned g_bits32[(long)MAX_N * MAX_WPG]; // packed adj1, 12.64 MB
__device__ float g_y1[MAX_N];
__device__ float g_y2[MAX_N];
__device__ int   g_flags[MAX_N];

// ---------------------------------------------------------------------------
// Flag kernel: mark nodes that appear in tar_ei (rows we must pack).
// ---------------------------------------------------------------------------
__global__ void flag_kernel(const int* __restrict__ tar, int cnt,
                            int* __restrict__ flags) {
    int i = blockIdx.x * blockDim.x + threadIdx.x;
    if (i < cnt) flags[tar[i]] = 1;
}

// ---------------------------------------------------------------------------
// Kernel 1: pack adj1 (row-major N x N, 4-byte bool words) into bitmasks.
// One block per row (skipped if unflagged). Each warp handles groups of 128
// columns: one uint4 load per lane (512B/warp contiguous), 4 ballots, one
// uint4 store of the ballots from lane 0.
// Bit layout: word index = group*4 + k (k = component 0..3),
//             bit 'lane' of that word = column group*128 + lane*4 + k.
// ---------------------------------------------------------------------------
__global__ void pack_adj_kernel(const unsigned int* __restrict__ adj,
                                const int* __restrict__ flags,
                                int n, int ngroups,
                                unsigned* __restrict__ bits) {
    int row = blockIdx.x;
    if (!flags[row]) return;
    int warp = threadIdx.x >> 5;
    int lane = threadIdx.x & 31;
    int nwarps = blockDim.x >> 5;

    const unsigned* rowp = adj + (long)row * n;
    unsigned* outp = bits + (long)row * (ngroups * 4);

    for (int g = warp; g < ngroups; g += nwarps) {
        int col0 = g * 128 + lane * 4;
        uint4 v = make_uint4(0u, 0u, 0u, 0u);
        if (col0 + 3 < n) {
            v = ((const uint4*)rowp)[g * 32 + lane];
        } else if (col0 < n) {
            const unsigned* p = rowp + col0;
            v.x = p[0];
            if (col0 + 1 < n) v.y = p[1];
            if (col0 + 2 < n) v.z = p[2];
        }
        unsigned b0 = __ballot_sync(0xFFFFFFFFu, v.x != 0u);
        unsigned b1 = __ballot_sync(0xFFFFFFFFu, v.y != 0u);
        unsigned b2 = __ballot_sync(0xFFFFFFFFu, v.z != 0u);
        unsigned b3 = __ballot_sync(0xFFFFFFFFu, v.w != 0u);
        if (lane == 0)
            *(uint4*)(outp + g * 4) = make_uint4(b0, b1, b2, b3);
    }
}

// ---------------------------------------------------------------------------
// Kernel 2: per-node projections y1[n] = x[n].W1, y2[n] = x[n].W2
// ---------------------------------------------------------------------------
__global__ void node_y_kernel(const float* __restrict__ x,
                              const float* __restrict__ W,   // [1, 3*DIM]
                              int n,
                              float* __restrict__ y1,
                              float* __restrict__ y2) {
    int warp = (blockIdx.x * blockDim.x + threadIdx.x) >> 5;
    int lane = threadIdx.x & 31;
    if (warp >= n) return;
    const float4* xr = (const float4*)(x + (long)warp * DIM);
    const float4* w1 = (const float4*)(W + DIM);
    const float4* w2 = (const float4*)(W + 2 * DIM);
    float s1 = 0.f, s2 = 0.f;
#pragma unroll
    for (int k = 0; k < 2; k++) {
        int i = lane * 2 + k;                  // 64 float4 per row
        float4 xv = xr[i];
        float4 a  = w1[i];
        float4 b  = w2[i];
        s1 += xv.x * a.x + xv.y * a.y + xv.z * a.z + xv.w * a.w;
        s2 += xv.x * b.x + xv.y * b.y + xv.z * b.z + xv.w * b.w;
    }
#pragma unroll
    for (int o = 16; o; o >>= 1) {
        s1 += __shfl_xor_sync(0xFFFFFFFFu, s1, o);
        s2 += __shfl_xor_sync(0xFFFFFFFFu, s2, o);
    }
    if (lane == 0) { y1[warp] = s1; y2[warp] = s2; }
}

// ---------------------------------------------------------------------------
// Kernel 3: per-edge output. One warp per edge.
// Bit layout (see pack): word w -> group w>>2, k = w&3; bit b of word w is
// node (w>>2)*128 + b*4 + k.
// ---------------------------------------------------------------------------
__device__ __forceinline__ int getbit(const unsigned* __restrict__ bits,
                                      int wpg, int a, int b) {
    unsigned word = bits[(long)a * wpg + (b >> 7) * 4 + (b & 3)];
    return (int)((word >> ((b & 127) >> 2)) & 1u);
}

__global__ void edge_kernel(const float* __restrict__ x,
                            const int* __restrict__ tar,      // [2, E]
                            const float* __restrict__ W,      // [1, 3*DIM]
                            const float* __restrict__ bxs,
                            int e_cnt, int wpg,
                            const unsigned* __restrict__ bits,
                            const float* __restrict__ y1,
                            const float* __restrict__ y2,
                            float* __restrict__ out) {
    int warp = (blockIdx.x * blockDim.x + threadIdx.x) >> 5;
    int lane = threadIdx.x & 31;
    if (warp >= e_cnt) return;

    int ti = tar[warp];
    int tj = tar[e_cnt + warp];

    const unsigned* A = bits + (long)ti * wpg;
    const unsigned* B = bits + (long)tj * wpg;

    float s = 0.f;
    // common 1-hop neighbors: AND of bitmask rows (rows live in L2)
    for (int w = lane; w < wpg; w += 32) {
        unsigned m = A[w] & B[w];
        int base = (w >> 2) * 128 + (w & 3);
        while (m) {
            int b = __ffs(m) - 1;
            m &= m - 1;
            s += y2[base + b * 4];
        }
    }

    // xij . W0 term
    const float4* xi = (const float4*)(x + (long)ti * DIM);
    const float4* xj = (const float4*)(x + (long)tj * DIM);
    const float4* w0 = (const float4*)W;
#pragma unroll
    for (int k = 0; k < 2; k++) {
        int i = lane * 2 + k;
        float4 a  = xi[i];
        float4 b4 = xj[i];
        float4 w  = w0[i];
        s += a.x * b4.x * w.x + a.y * b4.y * w.y
           + a.z * b4.z * w.z + a.w * b4.w * w.w;
    }

#pragma unroll
    for (int o = 16; o; o >>= 1)
        s += __shfl_xor_sync(0xFFFFFFFFu, s, o);

    if (lane == 0) {
        // cn0 corrections (hop-0+1 common minus hop-1 common): only ti, tj
        float s0 = 0.f;
        if (ti == tj) {
            if (!getbit(bits, wpg, ti, ti)) s0 = y1[ti];
        } else {
            if (getbit(bits, wpg, tj, ti) && !getbit(bits, wpg, ti, ti)) s0 += y1[ti];
            if (getbit(bits, wpg, ti, tj) && !getbit(bits, wpg, tj, tj)) s0 += y1[tj];
        }
        out[warp] = s + s0 + bxs[0];
    }
}

// ---------------------------------------------------------------------------
// Launch
// Inputs (metadata order): x[N*D] f32, adj01[N*N], adj1[N*N], tar_ei[2*E] i32,
//                          Wxs[1*3D] f32, bxs[1] f32, NCN_mode i32 (==0)
// Output: [E, 1] f32
// ---------------------------------------------------------------------------
extern "C" void kernel_launch(void* const* d_in, const int* in_sizes, int n_in,
                              void* d_out, int out_size) {
    const float*        x    = (const float*)d_in[0];
    const unsigned int* adj1 = (const unsigned int*)d_in[2];  // bool as 4-byte words
    const int*          tar  = (const int*)d_in[3];
    const float*        Wxs  = (const float*)d_in[4];
    const float*        bxs  = (const float*)d_in[5];
    float*              out  = (float*)d_out;

    const int N = in_sizes[0] / DIM;            // 10000
    const int E = in_sizes[3] / 2;              // 8192
    const int NGRP = (N + 127) / 128;           // 79
    const int WPG  = NGRP * 4;                  // 316

    unsigned* bits;
    float *y1, *y2;
    int* flags;
    cudaGetSymbolAddress((void**)&bits, g_bits32);
    cudaGetSymbolAddress((void**)&y1, g_y1);
    cudaGetSymbolAddress((void**)&y2, g_y2);
    cudaGetSymbolAddress((void**)&flags, g_flags);

    // Flags: zero then scatter-mark rows referenced by tar_ei
    cudaMemsetAsync(flags, 0, (size_t)N * sizeof(int));
    flag_kernel<<<(2 * E + 255) / 256, 256>>>(tar, 2 * E, flags);

    // Kernel 1: pack flagged rows of adj1 -> bitmask (~322 MB streaming read)
    pack_adj_kernel<<<N, 256>>>(adj1, flags, N, NGRP, bits);

    // Kernel 2: per-node projections
    node_y_kernel<<<(N + 7) / 8, 256>>>(x, Wxs, N, y1, y2);

    // Kernel 3: per-edge output
    edge_kernel<<<(E + 7) / 8, 256>>>(x, tar, Wxs, bxs, E, WPG,
                                      bits, y1, y2, out);
    (void)n_in; (void)out_size;
}

// round 3
// speedup vs baseline: 1.9517x; 1.0007x over previous
#include <cuda_runtime.h>
#include <cuda_bf16.h>

// Problem constants (fixed by the dataset)
#define MAX_N 10000
#define DIM   256
// groups of 128 columns, 4 x uint32 per group
#define MAX_GRP ((MAX_N + 127) / 128)        // 79
#define MAX_WPG (MAX_GRP * 4)                // 316 uint32 words per row

// Scratch (device globals; no allocation allowed)
__device__ unsigned g_bits32[(long)MAX_N * MAX_WPG]; // packed adj1, 12.64 MB
__device__ float g_y1[MAX_N];
__device__ float g_y2[MAX_N];
__device__ int   g_flags[MAX_N];

// ---------------------------------------------------------------------------
// Flag kernel: mark nodes that appear in tar_ei (rows we must pack).
// ---------------------------------------------------------------------------
__global__ void flag_kernel(const int* __restrict__ tar, int cnt,
                            int* __restrict__ flags) {
    int i = blockIdx.x * blockDim.x + threadIdx.x;
    if (i < cnt) flags[tar[i]] = 1;
}

// ---------------------------------------------------------------------------
// Kernel 1: pack adj1 (row-major N x N, 4-byte bool words) into bitmasks.
// One block per row (skipped if unflagged). Each warp handles a BATCH of 4
// consecutive 128-column groups per iteration: 4 independent uint4 loads
// (2 KB/warp in flight) -> 16 ballots -> 4 contiguous uint4 stores.
// Bit layout: word index = group*4 + k (k = uint4 component 0..3),
//             bit 'lane' of that word = column group*128 + lane*4 + k.
// ---------------------------------------------------------------------------
__global__ void pack_adj_kernel(const unsigned int* __restrict__ adj,
                                const int* __restrict__ flags,
                                int n, int ngroups,
                                unsigned* __restrict__ bits) {
    int row = blockIdx.x;
    if (!flags[row]) return;
    int warp = threadIdx.x >> 5;
    int lane = threadIdx.x & 31;
    int nwarps = blockDim.x >> 5;

    const uint4* rowp4 = (const uint4*)(adj + (long)row * n);
    uint4* outp = (uint4*)(bits + (long)row * (ngroups * 4));

    for (int g0 = warp * 4; g0 < ngroups; g0 += nwarps * 4) {
        uint4 v[4];
        // Front-batched independent loads (MLP)
#pragma unroll
        for (int j = 0; j < 4; j++) {
            int g = g0 + j;
            v[j] = make_uint4(0u, 0u, 0u, 0u);
            if (g < ngroups) {
                int col0 = g * 128 + lane * 4;
                if (col0 + 3 < n) {
                    v[j] = rowp4[g * 32 + lane];
                } else if (col0 < n) {
                    const unsigned* p = (const unsigned*)rowp4 + col0;
                    v[j].x = p[0];
                    if (col0 + 1 < n) v[j].y = p[1];
                    if (col0 + 2 < n) v[j].z = p[2];
                }
            }
        }
#pragma unroll
        for (int j = 0; j < 4; j++) {
            unsigned b0 = __ballot_sync(0xFFFFFFFFu, v[j].x != 0u);
            unsigned b1 = __ballot_sync(0xFFFFFFFFu, v[j].y != 0u);
            unsigned b2 = __ballot_sync(0xFFFFFFFFu, v[j].z != 0u);
            unsigned b3 = __ballot_sync(0xFFFFFFFFu, v[j].w != 0u);
            if (lane == 0 && g0 + j < ngroups)
                outp[g0 + j] = make_uint4(b0, b1, b2, b3);
        }
    }
}

// ---------------------------------------------------------------------------
// Kernel 2: per-node projections y1[n] = x[n].W1, y2[n] = x[n].W2
// ---------------------------------------------------------------------------
__global__ void node_y_kernel(const float* __restrict__ x,
                              const float* __restrict__ W,   // [1, 3*DIM]
                              int n,
                              float* __restrict__ y1,
                              float* __restrict__ y2) {
    int warp = (blockIdx.x * blockDim.x + threadIdx.x) >> 5;
    int lane = threadIdx.x & 31;
    if (warp >= n) return;
    const float4* xr = (const float4*)(x + (long)warp * DIM);
    const float4* w1 = (const float4*)(W + DIM);
    const float4* w2 = (const float4*)(W + 2 * DIM);
    float s1 = 0.f, s2 = 0.f;
#pragma unroll
    for (int k = 0; k < 2; k++) {
        int i = lane * 2 + k;                  // 64 float4 per row
        float4 xv = xr[i];
        float4 a  = w1[i];
        float4 b  = w2[i];
        s1 += xv.x * a.x + xv.y * a.y + xv.z * a.z + xv.w * a.w;
        s2 += xv.x * b.x + xv.y * b.y + xv.z * b.z + xv.w * b.w;
    }
#pragma unroll
    for (int o = 16; o; o >>= 1) {
        s1 += __shfl_xor_sync(0xFFFFFFFFu, s1, o);
        s2 += __shfl_xor_sync(0xFFFFFFFFu, s2, o);
    }
    if (lane == 0) { y1[warp] = s1; y2[warp] = s2; }
}

// ---------------------------------------------------------------------------
// Kernel 3: per-edge output. One warp per edge.
// Bit layout (see pack): word w -> group w>>2, k = w&3; bit b of word w is
// node (w>>2)*128 + b*4 + k. uint4 loads fetch a whole group at once.
// ---------------------------------------------------------------------------
__device__ __forceinline__ int getbit(const unsigned* __restrict__ bits,
                                      int wpg, int a, int b) {
    unsigned word = bits[(long)a * wpg + (b >> 7) * 4 + (b & 3)];
    return (int)((word >> ((b & 127) >> 2)) & 1u);
}

__global__ void edge_kernel(const float* __restrict__ x,
                            const int* __restrict__ tar,      // [2, E]
                            const float* __restrict__ W,      // [1, 3*DIM]
                            const float* __restrict__ bxs,
                            int e_cnt, int ngroups,
                            const unsigned* __restrict__ bits,
                            const float* __restrict__ y1,
                            const float* __restrict__ y2,
                            float* __restrict__ out) {
    int warp = (blockIdx.x * blockDim.x + threadIdx.x) >> 5;
    int lane = threadIdx.x & 31;
    if (warp >= e_cnt) return;

    int ti = tar[warp];
    int tj = tar[e_cnt + warp];
    int wpg = ngroups * 4;

    const uint4* A = (const uint4*)(bits + (long)ti * wpg);
    const uint4* B = (const uint4*)(bits + (long)tj * wpg);

    float s = 0.f;
    // common 1-hop neighbors: AND of bitmask rows (uint4 per 128-col group)
    for (int g = lane; g < ngroups; g += 32) {
        uint4 a = A[g];
        uint4 b = B[g];
        unsigned m0 = a.x & b.x, m1 = a.y & b.y;
        unsigned m2 = a.z & b.z, m3 = a.w & b.w;
        int base = g * 128;
        while (m0) { int bb = __ffs(m0) - 1; m0 &= m0 - 1; s += y2[base + bb * 4 + 0]; }
        while (m1) { int bb = __ffs(m1) - 1; m1 &= m1 - 1; s += y2[base + bb * 4 + 1]; }
        while (m2) { int bb = __ffs(m2) - 1; m2 &= m2 - 1; s += y2[base + bb * 4 + 2]; }
        while (m3) { int bb = __ffs(m3) - 1; m3 &= m3 - 1; s += y2[base + bb * 4 + 3]; }
    }

    // xij . W0 term
    const float4* xi = (const float4*)(x + (long)ti * DIM);
    const float4* xj = (const float4*)(x + (long)tj * DIM);
    const float4* w0 = (const float4*)W;
#pragma unroll
    for (int k = 0; k < 2; k++) {
        int i = lane * 2 + k;
        float4 a  = xi[i];
        float4 b4 = xj[i];
        float4 w  = w0[i];
        s += a.x * b4.x * w.x + a.y * b4.y * w.y
           + a.z * b4.z * w.z + a.w * b4.w * w.w;
    }

#pragma unroll
    for (int o = 16; o; o >>= 1)
        s += __shfl_xor_sync(0xFFFFFFFFu, s, o);

    if (lane == 0) {
        // cn0 corrections (hop-0+1 common minus hop-1 common): only ti, tj
        float s0 = 0.f;
        if (ti == tj) {
            if (!getbit(bits, wpg, ti, ti)) s0 = y1[ti];
        } else {
            if (getbit(bits, wpg, tj, ti) && !getbit(bits, wpg, ti, ti)) s0 += y1[ti];
            if (getbit(bits, wpg, ti, tj) && !getbit(bits, wpg, tj, tj)) s0 += y1[tj];
        }
        out[warp] = s + s0 + bxs[0];
    }
}

// ---------------------------------------------------------------------------
// Launch
// Inputs (metadata order): x[N*D] f32, adj01[N*N], adj1[N*N], tar_ei[2*E] i32,
//                          Wxs[1*3D] f32, bxs[1] f32, NCN_mode i32 (==0)
// Output: [E, 1] f32
// ---------------------------------------------------------------------------
extern "C" void kernel_launch(void* const* d_in, const int* in_sizes, int n_in,
                              void* d_out, int out_size) {
    const float*        x    = (const float*)d_in[0];
    const unsigned int* adj1 = (const unsigned int*)d_in[2];  // bool as 4-byte words
    const int*          tar  = (const int*)d_in[3];
    const float*        Wxs  = (const float*)d_in[4];
    const float*        bxs  = (const float*)d_in[5];
    float*              out  = (float*)d_out;

    const int N = in_sizes[0] / DIM;            // 10000
    const int E = in_sizes[3] / 2;              // 8192
    const int NGRP = (N + 127) / 128;           // 79

    unsigned* bits;
    float *y1, *y2;
    int* flags;
    cudaGetSymbolAddress((void**)&bits, g_bits32);
    cudaGetSymbolAddress((void**)&y1, g_y1);
    cudaGetSymbolAddress((void**)&y2, g_y2);
    cudaGetSymbolAddress((void**)&flags, g_flags);

    // Flags: zero then scatter-mark rows referenced by tar_ei
    cudaMemsetAsync(flags, 0, (size_t)N * sizeof(int));
    flag_kernel<<<(2 * E + 255) / 256, 256>>>(tar, 2 * E, flags);

    // Kernel 1: pack flagged rows of adj1 -> bitmask (~322 MB streaming read)
    pack_adj_kernel<<<N, 256>>>(adj1, flags, N, NGRP, bits);

    // Kernel 2: per-node projections
    node_y_kernel<<<(N + 7) / 8, 256>>>(x, Wxs, N, y1, y2);

    // Kernel 3: per-edge output
    edge_kernel<<<(E + 7) / 8, 256>>>(x, tar, Wxs, bxs, E, NGRP,
                                      bits, y1, y2, out);
    (void)n_in; (void)out_size;
}

// round 4
// speedup vs baseline: 2.2659x; 1.1610x over previous
#include <cuda_runtime.h>
#include <cuda_bf16.h>

// Problem constants (fixed by the dataset)
#define MAX_N 10000
#define DIM   256
// groups of 128 columns, 4 x uint32 per group
#define MAX_GRP ((MAX_N + 127) / 128)        // 79
#define MAX_WPG (MAX_GRP * 4)                // 316 uint32 words per row

// Scratch (device globals; no allocation allowed)
__device__ unsigned g_bits32[(long)MAX_N * MAX_WPG]; // packed adj1, 12.64 MB
__device__ float g_y1[MAX_N];
__device__ float g_y2[MAX_N];
__device__ int   g_flags[MAX_N];

// ---------------------------------------------------------------------------
// Flag kernel: mark nodes that appear in tar_ei (rows we must pack).
// ---------------------------------------------------------------------------
__global__ void flag_kernel(const int* __restrict__ tar, int cnt,
                            int* __restrict__ flags) {
    int i = blockIdx.x * blockDim.x + threadIdx.x;
    if (i < cnt) flags[tar[i]] = 1;
}

// ---------------------------------------------------------------------------
// Kernel: per-node projections y1[n] = x[n].W1, y2[n] = x[n].W2
// ---------------------------------------------------------------------------
__global__ void node_y_kernel(const float* __restrict__ x,
                              const float* __restrict__ W,   // [1, 3*DIM]
                              int n,
                              float* __restrict__ y1,
                              float* __restrict__ y2) {
    int warp = (blockIdx.x * blockDim.x + threadIdx.x) >> 5;
    int lane = threadIdx.x & 31;
    if (warp >= n) return;
    const float4* xr = (const float4*)(x + (long)warp * DIM);
    const float4* w1 = (const float4*)(W + DIM);
    const float4* w2 = (const float4*)(W + 2 * DIM);
    float s1 = 0.f, s2 = 0.f;
#pragma unroll
    for (int k = 0; k < 2; k++) {
        int i = lane * 2 + k;                  // 64 float4 per row
        float4 xv = xr[i];
        float4 a  = w1[i];
        float4 b  = w2[i];
        s1 += xv.x * a.x + xv.y * a.y + xv.z * a.z + xv.w * a.w;
        s2 += xv.x * b.x + xv.y * b.y + xv.z * b.z + xv.w * b.w;
    }
#pragma unroll
    for (int o = 16; o; o >>= 1) {
        s1 += __shfl_xor_sync(0xFFFFFFFFu, s1, o);
        s2 += __shfl_xor_sync(0xFFFFFFFFu, s2, o);
    }
    if (lane == 0) { y1[warp] = s1; y2[warp] = s2; }
}

// ---------------------------------------------------------------------------
// edge_dot: out[e] = xij.W0 + cn0 corrections (raw adj1 bits) + bias.
// Independent of pack -> runs CONCURRENTLY with pack via PDL.
// One warp per edge; grid sized to a single wave; triggers PDL at block start.
// ---------------------------------------------------------------------------
__global__ void edge_dot_kernel(const float* __restrict__ x,
                                const int* __restrict__ tar,   // [2, E]
                                const float* __restrict__ W,   // [1, 3*DIM]
                                const float* __restrict__ bxs,
                                const unsigned* __restrict__ adj, // raw adj1
                                int n, int e_cnt,
                                const float* __restrict__ y1,
                                float* __restrict__ out) {
    cudaTriggerProgrammaticLaunchCompletion();
    int warp = (blockIdx.x * blockDim.x + threadIdx.x) >> 5;
    int lane = threadIdx.x & 31;
    if (warp >= e_cnt) return;

    int ti = tar[warp];
    int tj = tar[e_cnt + warp];

    // cn0 correction bits straight from the raw bool matrix (4 scalar loads,
    // issued up-front so they overlap the dot-product loads).
    unsigned aii = 0, ajj = 0, aij = 0, aji = 0;
    if (lane == 0) {
        aii = adj[(long)ti * n + ti];
        aji = adj[(long)tj * n + ti];
        aij = adj[(long)ti * n + tj];
        ajj = adj[(long)tj * n + tj];
    }

    const float4* xi = (const float4*)(x + (long)ti * DIM);
    const float4* xj = (const float4*)(x + (long)tj * DIM);
    const float4* w0 = (const float4*)W;
    float s = 0.f;
#pragma unroll
    for (int k = 0; k < 2; k++) {
        int i = lane * 2 + k;
        float4 a  = xi[i];
        float4 b4 = xj[i];
        float4 w  = w0[i];
        s += a.x * b4.x * w.x + a.y * b4.y * w.y
           + a.z * b4.z * w.z + a.w * b4.w * w.w;
    }
#pragma unroll
    for (int o = 16; o; o >>= 1)
        s += __shfl_xor_sync(0xFFFFFFFFu, s, o);

    if (lane == 0) {
        float s0 = 0.f;
        if (ti == tj) {
            if (!aii) s0 = y1[ti];
        } else {
            if (aji && !aii) s0 += y1[ti];
            if (aij && !ajj) s0 += y1[tj];
        }
        out[warp] = s + s0 + bxs[0];
    }
}

// ---------------------------------------------------------------------------
// pack: adj1 (row-major N x N, 4-byte bool words) -> bitmasks.
// Round-2 structure (proven 5.4 TB/s): one uint4 load / 4 ballots / one
// uint4 store per warp-iteration. __ldcs: adj stream is evict-first so the
// bits output stays resident in L2 for edge_cn.
// Bit layout: word = group*4 + k; bit 'lane' of that word
//             = column group*128 + lane*4 + k.
// Launched with PSS=1 so it overlaps edge_dot.
// ---------------------------------------------------------------------------
__global__ void pack_adj_kernel(const unsigned int* __restrict__ adj,
                                const int* __restrict__ flags,
                                int n, int ngroups,
                                unsigned* __restrict__ bits) {
    int row = blockIdx.x;
    if (!flags[row]) return;
    int warp = threadIdx.x >> 5;
    int lane = threadIdx.x & 31;
    int nwarps = blockDim.x >> 5;

    const uint4* rowp4 = (const uint4*)(adj + (long)row * n);
    const unsigned* rowp = adj + (long)row * n;
    uint4* outp = (uint4*)(bits + (long)row * (ngroups * 4));

    for (int g = warp; g < ngroups; g += nwarps) {
        int col0 = g * 128 + lane * 4;
        uint4 v = make_uint4(0u, 0u, 0u, 0u);
        if (col0 + 3 < n) {
            v = __ldcs(&rowp4[g * 32 + lane]);
        } else if (col0 < n) {
            v.x = rowp[col0];
            if (col0 + 1 < n) v.y = rowp[col0 + 1];
            if (col0 + 2 < n) v.z = rowp[col0 + 2];
        }
        unsigned b0 = __ballot_sync(0xFFFFFFFFu, v.x != 0u);
        unsigned b1 = __ballot_sync(0xFFFFFFFFu, v.y != 0u);
        unsigned b2 = __ballot_sync(0xFFFFFFFFu, v.z != 0u);
        unsigned b3 = __ballot_sync(0xFFFFFFFFu, v.w != 0u);
        if (lane == 0)
            outp[g] = make_uint4(b0, b1, b2, b3);
    }
}

// ---------------------------------------------------------------------------
// edge_cn: out[e] += sum_{n in cn1(e)} y2[n].  Needs pack complete.
// Bits rows live in L2 (12.6 MB). One warp per edge, uint4 per 128-col group.
// ---------------------------------------------------------------------------
__global__ void edge_cn_kernel(const int* __restrict__ tar,   // [2, E]
                               int e_cnt, int ngroups,
                               const unsigned* __restrict__ bits,
                               const float* __restrict__ y2,
                               float* __restrict__ out) {
    int warp = (blockIdx.x * blockDim.x + threadIdx.x) >> 5;
    int lane = threadIdx.x & 31;
    if (warp >= e_cnt) return;

    int ti = tar[warp];
    int tj = tar[e_cnt + warp];
    int wpg = ngroups * 4;

    const uint4* A = (const uint4*)(bits + (long)ti * wpg);
    const uint4* B = (const uint4*)(bits + (long)tj * wpg);

    float s = 0.f;
    for (int g = lane; g < ngroups; g += 32) {
        uint4 a = A[g];
        uint4 b = B[g];
        unsigned m0 = a.x & b.x, m1 = a.y & b.y;
        unsigned m2 = a.z & b.z, m3 = a.w & b.w;
        int base = g * 128;
        while (m0) { int bb = __ffs(m0) - 1; m0 &= m0 - 1; s += y2[base + bb * 4 + 0]; }
        while (m1) { int bb = __ffs(m1) - 1; m1 &= m1 - 1; s += y2[base + bb * 4 + 1]; }
        while (m2) { int bb = __ffs(m2) - 1; m2 &= m2 - 1; s += y2[base + bb * 4 + 2]; }
        while (m3) { int bb = __ffs(m3) - 1; m3 &= m3 - 1; s += y2[base + bb * 4 + 3]; }
    }
#pragma unroll
    for (int o = 16; o; o >>= 1)
        s += __shfl_xor_sync(0xFFFFFFFFu, s, o);

    if (lane == 0 && s != 0.f)
        out[warp] += s;
}

// ---------------------------------------------------------------------------
// Launch
// Inputs (metadata order): x[N*D] f32, adj01[N*N], adj1[N*N], tar_ei[2*E] i32,
//                          Wxs[1*3D] f32, bxs[1] f32, NCN_mode i32 (==0)
// Output: [E, 1] f32
// Stream order: flags, node_y, edge_dot(trigger), pack(PSS=1, overlapped),
//               edge_cn (waits for all).
// ---------------------------------------------------------------------------
extern "C" void kernel_launch(void* const* d_in, const int* in_sizes, int n_in,
                              void* d_out, int out_size) {
    const float*        x    = (const float*)d_in[0];
    const unsigned int* adj1 = (const unsigned int*)d_in[2];  // bool as 4-byte words
    const int*          tar  = (const int*)d_in[3];
    const float*        Wxs  = (const float*)d_in[4];
    const float*        bxs  = (const float*)d_in[5];
    float*              out  = (float*)d_out;

    const int N = in_sizes[0] / DIM;            // 10000
    const int E = in_sizes[3] / 2;              // 8192
    const int NGRP = (N + 127) / 128;           // 79

    unsigned* bits;
    float *y1, *y2;
    int* flags;
    cudaGetSymbolAddress((void**)&bits, g_bits32);
    cudaGetSymbolAddress((void**)&y1, g_y1);
    cudaGetSymbolAddress((void**)&y2, g_y2);
    cudaGetSymbolAddress((void**)&flags, g_flags);

    // Flags: zero then scatter-mark rows referenced by tar_ei
    cudaMemsetAsync(flags, 0, (size_t)N * sizeof(int));
    flag_kernel<<<(2 * E + 255) / 256, 256>>>(tar, 2 * E, flags);

    // Per-node projections (needed by edge_dot's cn0 corrections)
    node_y_kernel<<<(N + 7) / 8, 256>>>(x, Wxs, N, y1, y2);

    // edge_dot: single-wave grid (1024 blocks), PDL trigger at block start
    edge_dot_kernel<<<(E + 7) / 8, 256>>>(x, tar, Wxs, bxs, adj1, N, E, y1, out);

    // pack: launched with programmatic stream serialization -> begins as soon
    // as edge_dot's blocks have launched + triggered; runs concurrently.
    {
        cudaLaunchConfig_t cfg = {};
        cfg.gridDim  = dim3((unsigned)N);
        cfg.blockDim = dim3(256);
        cudaLaunchAttribute attr[1];
        attr[0].id = cudaLaunchAttributeProgrammaticStreamSerialization;
        attr[0].val.programmaticStreamSerializationAllowed = 1;
        cfg.attrs = attr;
        cfg.numAttrs = 1;
        cudaLaunchKernelEx(&cfg, pack_adj_kernel, adj1,
                           (const int*)flags, N, NGRP, (unsigned*)bits);
    }

    // edge_cn: plain launch -> waits for pack (and edge_dot) completion
    edge_cn_kernel<<<(E + 7) / 8, 256>>>(tar, E, NGRP, bits, y2, out);

    (void)n_in; (void)out_size;
}

// round 5
// speedup vs baseline: 2.5126x; 1.1089x over previous
#include <cuda_runtime.h>
#include <cuda_bf16.h>

// Problem constants (fixed by the dataset)
#define MAX_N 10000
#define DIM   256
// groups of 128 columns, 4 x uint32 per group
#define MAX_GRP ((MAX_N + 127) / 128)        // 79
#define MAX_WPG (MAX_GRP * 4)                // 316 uint32 words per row

// Scratch (device globals; no allocation allowed)
__device__ unsigned g_bits32[(long)MAX_N * MAX_WPG]; // packed adj1, 12.64 MB
__device__ float g_y1[MAX_N];
__device__ float g_y2[MAX_N];
__device__ int   g_flags[MAX_N];

// ---------------------------------------------------------------------------
// Flag kernel: mark nodes that appear in tar_ei (rows we must pack).
// ---------------------------------------------------------------------------
__global__ void flag_kernel(const int* __restrict__ tar, int cnt,
                            int* __restrict__ flags) {
    int i = blockIdx.x * blockDim.x + threadIdx.x;
    if (i < cnt) flags[tar[i]] = 1;
}

// ---------------------------------------------------------------------------
// Kernel: per-node projections y1[n] = x[n].W1, y2[n] = x[n].W2
// ---------------------------------------------------------------------------
__global__ void node_y_kernel(const float* __restrict__ x,
                              const float* __restrict__ W,   // [1, 3*DIM]
                              int n,
                              float* __restrict__ y1,
                              float* __restrict__ y2) {
    int warp = (blockIdx.x * blockDim.x + threadIdx.x) >> 5;
    int lane = threadIdx.x & 31;
    if (warp >= n) return;
    const float4* xr = (const float4*)(x + (long)warp * DIM);
    const float4* w1 = (const float4*)(W + DIM);
    const float4* w2 = (const float4*)(W + 2 * DIM);
    float s1 = 0.f, s2 = 0.f;
#pragma unroll
    for (int k = 0; k < 2; k++) {
        int i = lane * 2 + k;                  // 64 float4 per row
        float4 xv = xr[i];
        float4 a  = w1[i];
        float4 b  = w2[i];
        s1 += xv.x * a.x + xv.y * a.y + xv.z * a.z + xv.w * a.w;
        s2 += xv.x * b.x + xv.y * b.y + xv.z * b.z + xv.w * b.w;
    }
#pragma unroll
    for (int o = 16; o; o >>= 1) {
        s1 += __shfl_xor_sync(0xFFFFFFFFu, s1, o);
        s2 += __shfl_xor_sync(0xFFFFFFFFu, s2, o);
    }
    if (lane == 0) { y1[warp] = s1; y2[warp] = s2; }
}

// ---------------------------------------------------------------------------
// edge_dot: out[e] = xij.W0 + cn0 corrections (raw adj1 bits) + bias.
// Independent of pack -> runs CONCURRENTLY with pack via PDL.
// ---------------------------------------------------------------------------
__global__ void edge_dot_kernel(const float* __restrict__ x,
                                const int* __restrict__ tar,   // [2, E]
                                const float* __restrict__ W,   // [1, 3*DIM]
                                const float* __restrict__ bxs,
                                const unsigned* __restrict__ adj, // raw adj1
                                int n, int e_cnt,
                                const float* __restrict__ y1,
                                float* __restrict__ out) {
    cudaTriggerProgrammaticLaunchCompletion();
    int warp = (blockIdx.x * blockDim.x + threadIdx.x) >> 5;
    int lane = threadIdx.x & 31;
    if (warp >= e_cnt) return;

    int ti = tar[warp];
    int tj = tar[e_cnt + warp];

    // cn0 correction bits straight from the raw bool matrix (rare-taken).
    unsigned aii = 0, ajj = 0, aij = 0, aji = 0;
    if (lane == 0) {
        aii = adj[(long)ti * n + ti];
        aji = adj[(long)tj * n + ti];
        aij = adj[(long)ti * n + tj];
        ajj = adj[(long)tj * n + tj];
    }

    const float4* xi = (const float4*)(x + (long)ti * DIM);
    const float4* xj = (const float4*)(x + (long)tj * DIM);
    const float4* w0 = (const float4*)W;
    float s = 0.f;
#pragma unroll
    for (int k = 0; k < 2; k++) {
        int i = lane * 2 + k;
        float4 a  = xi[i];
        float4 b4 = xj[i];
        float4 w  = w0[i];
        s += a.x * b4.x * w.x + a.y * b4.y * w.y
           + a.z * b4.z * w.z + a.w * b4.w * w.w;
    }
#pragma unroll
    for (int o = 16; o; o >>= 1)
        s += __shfl_xor_sync(0xFFFFFFFFu, s, o);

    if (lane == 0) {
        float s0 = 0.f;
        if (ti == tj) {
            if (!aii) s0 = y1[ti];
        } else {
            if (aji && !aii) s0 += y1[ti];
            if (aij && !ajj) s0 += y1[tj];
        }
        out[warp] = s + s0 + bxs[0];
    }
}

// ---------------------------------------------------------------------------
// pack: adj1 (row-major N x N, 4-byte bool words) -> bitmasks.
// MLP=2 hot loop: each warp-iteration issues TWO independent uint4 streaming
// loads (1 KB/warp in flight), 8 ballots, and two PARALLEL uint4 stores
// (ballot results are warp-uniform: lane 0 stores group 2p, lane 1 stores
// group 2p+1). Groups 0..(2*npairs-1) need NO bounds checks (N=10000 ->
// group 77 ends at col 9983). The odd tail group is a cold path on warp 0.
// Bit layout: word = group*4 + k; bit 'lane' = column group*128 + lane*4 + k.
// ---------------------------------------------------------------------------
__global__ void pack_adj_kernel(const unsigned int* __restrict__ adj,
                                const int* __restrict__ flags,
                                int n, int ngroups,
                                unsigned* __restrict__ bits) {
    int row = blockIdx.x;
    if (!flags[row]) return;
    int warp = threadIdx.x >> 5;
    int lane = threadIdx.x & 31;
    int nwarps = blockDim.x >> 5;

    const uint4* rowp4 = (const uint4*)(adj + (long)row * n);
    uint4* outp = (uint4*)(bits + (long)row * (ngroups * 4));

    int npairs = ngroups >> 1;                 // 39 full pairs (groups 0..77)
    for (int p = warp; p < npairs; p += nwarps) {
        int g0 = p * 2;
        // two independent streaming loads
        uint4 v0 = __ldcs(&rowp4[g0 * 32 + lane]);
        uint4 v1 = __ldcs(&rowp4[g0 * 32 + 32 + lane]);
        unsigned b0 = __ballot_sync(0xFFFFFFFFu, v0.x != 0u);
        unsigned b1 = __ballot_sync(0xFFFFFFFFu, v0.y != 0u);
        unsigned b2 = __ballot_sync(0xFFFFFFFFu, v0.z != 0u);
        unsigned b3 = __ballot_sync(0xFFFFFFFFu, v0.w != 0u);
        unsigned b4 = __ballot_sync(0xFFFFFFFFu, v1.x != 0u);
        unsigned b5 = __ballot_sync(0xFFFFFFFFu, v1.y != 0u);
        unsigned b6 = __ballot_sync(0xFFFFFFFFu, v1.z != 0u);
        unsigned b7 = __ballot_sync(0xFFFFFFFFu, v1.w != 0u);
        // ballot results are uniform across the warp: two lanes store in parallel
        if (lane == 0)      outp[g0]     = make_uint4(b0, b1, b2, b3);
        else if (lane == 1) outp[g0 + 1] = make_uint4(b4, b5, b6, b7);
    }

    // tail: remaining odd group(s), cold path (group 78 for N=10000)
    if (warp == 0) {
        for (int g = npairs * 2; g < ngroups; g++) {
            int col0 = g * 128 + lane * 4;
            uint4 v = make_uint4(0u, 0u, 0u, 0u);
            if (col0 + 3 < n) {
                v = __ldcs(&rowp4[g * 32 + lane]);
            } else if (col0 < n) {
                const unsigned* p = adj + (long)row * n + col0;
                v.x = p[0];
                if (col0 + 1 < n) v.y = p[1];
                if (col0 + 2 < n) v.z = p[2];
            }
            unsigned b0 = __ballot_sync(0xFFFFFFFFu, v.x != 0u);
            unsigned b1 = __ballot_sync(0xFFFFFFFFu, v.y != 0u);
            unsigned b2 = __ballot_sync(0xFFFFFFFFu, v.z != 0u);
            unsigned b3 = __ballot_sync(0xFFFFFFFFu, v.w != 0u);
            if (lane == 0)
                outp[g] = make_uint4(b0, b1, b2, b3);
        }
    }
}

// ---------------------------------------------------------------------------
// edge_cn: out[e] += sum_{n in cn1(e)} y2[n].  Needs pack complete.
// Bits rows live in L2 (12.6 MB). One warp per edge, uint4 per 128-col group.
// ---------------------------------------------------------------------------
__global__ void edge_cn_kernel(const int* __restrict__ tar,   // [2, E]
                               int e_cnt, int ngroups,
                               const unsigned* __restrict__ bits,
                               const float* __restrict__ y2,
                               float* __restrict__ out) {
    int warp = (blockIdx.x * blockDim.x + threadIdx.x) >> 5;
    int lane = threadIdx.x & 31;
    if (warp >= e_cnt) return;

    int ti = tar[warp];
    int tj = tar[e_cnt + warp];
    int wpg = ngroups * 4;

    const uint4* A = (const uint4*)(bits + (long)ti * wpg);
    const uint4* B = (const uint4*)(bits + (long)tj * wpg);

    float s = 0.f;
    for (int g = lane; g < ngroups; g += 32) {
        uint4 a = A[g];
        uint4 b = B[g];
        unsigned m0 = a.x & b.x, m1 = a.y & b.y;
        unsigned m2 = a.z & b.z, m3 = a.w & b.w;
        int base = g * 128;
        while (m0) { int bb = __ffs(m0) - 1; m0 &= m0 - 1; s += y2[base + bb * 4 + 0]; }
        while (m1) { int bb = __ffs(m1) - 1; m1 &= m1 - 1; s += y2[base + bb * 4 + 1]; }
        while (m2) { int bb = __ffs(m2) - 1; m2 &= m2 - 1; s += y2[base + bb * 4 + 2]; }
        while (m3) { int bb = __ffs(m3) - 1; m3 &= m3 - 1; s += y2[base + bb * 4 + 3]; }
    }
#pragma unroll
    for (int o = 16; o; o >>= 1)
        s += __shfl_xor_sync(0xFFFFFFFFu, s, o);

    if (lane == 0 && s != 0.f)
        out[warp] += s;
}

// ---------------------------------------------------------------------------
// Launch
// Inputs (metadata order): x[N*D] f32, adj01[N*N], adj1[N*N], tar_ei[2*E] i32,
//                          Wxs[1*3D] f32, bxs[1] f32, NCN_mode i32 (==0)
// Output: [E, 1] f32
// Stream order: flags, node_y, edge_dot(trigger), pack(PSS=1, overlapped),
//               edge_cn (waits pack; pack >> edge_dot so ordering holds).
// ---------------------------------------------------------------------------
extern "C" void kernel_launch(void* const* d_in, const int* in_sizes, int n_in,
                              void* d_out, int out_size) {
    const float*        x    = (const float*)d_in[0];
    const unsigned int* adj1 = (const unsigned int*)d_in[2];  // bool as 4-byte words
    const int*          tar  = (const int*)d_in[3];
    const float*        Wxs  = (const float*)d_in[4];
    const float*        bxs  = (const float*)d_in[5];
    float*              out  = (float*)d_out;

    const int N = in_sizes[0] / DIM;            // 10000
    const int E = in_sizes[3] / 2;              // 8192
    const int NGRP = (N + 127) / 128;           // 79

    unsigned* bits;
    float *y1, *y2;
    int* flags;
    cudaGetSymbolAddress((void**)&bits, g_bits32);
    cudaGetSymbolAddress((void**)&y1, g_y1);
    cudaGetSymbolAddress((void**)&y2, g_y2);
    cudaGetSymbolAddress((void**)&flags, g_flags);

    // Flags: zero then scatter-mark rows referenced by tar_ei
    cudaMemsetAsync(flags, 0, (size_t)N * sizeof(int));
    flag_kernel<<<(2 * E + 255) / 256, 256>>>(tar, 2 * E, flags);

    // Per-node projections (needed by edge_dot's cn0 corrections)
    node_y_kernel<<<(N + 7) / 8, 256>>>(x, Wxs, N, y1, y2);

    // edge_dot: single-wave grid (1024 blocks), PDL trigger at block start
    edge_dot_kernel<<<(E + 7) / 8, 256>>>(x, tar, Wxs, bxs, adj1, N, E, y1, out);

    // pack: programmatic stream serialization -> overlaps edge_dot.
    {
        cudaLaunchConfig_t cfg = {};
        cfg.gridDim  = dim3((unsigned)N);
        cfg.blockDim = dim3(256);
        cudaLaunchAttribute attr[1];
        attr[0].id = cudaLaunchAttributeProgrammaticStreamSerialization;
        attr[0].val.programmaticStreamSerializationAllowed = 1;
        cfg.attrs = attr;
        cfg.numAttrs = 1;
        cudaLaunchKernelEx(&cfg, pack_adj_kernel, adj1,
                           (const int*)flags, N, NGRP, (unsigned*)bits);
    }

    // edge_cn: plain launch -> waits for pack completion
    edge_cn_kernel<<<(E + 7) / 8, 256>>>(tar, E, NGRP, bits, y2, out);

    (void)n_in; (void)out_size;
}

// round 6
// speedup vs baseline: 2.5173x; 1.0019x over previous
#include <cuda_runtime.h>
#include <cuda_bf16.h>

// Problem constants (fixed by the dataset)
#define MAX_N 10000
#define DIM   256
// groups of 128 columns, 4 x uint32 per group
#define MAX_GRP ((MAX_N + 127) / 128)        // 79
#define MAX_WPG (MAX_GRP * 4)                // 316 uint32 words per row

// Scratch (device globals; no allocation allowed)
__device__ unsigned g_bits32[(long)MAX_N * MAX_WPG]; // packed adj1, 12.64 MB
__device__ float g_y1[MAX_N];
__device__ float g_y2[MAX_N];
__device__ int   g_flags[MAX_N];

// ---------------------------------------------------------------------------
// Flag kernel: mark nodes that appear in tar_ei (rows we must pack).
// ---------------------------------------------------------------------------
__global__ void flag_kernel(const int* __restrict__ tar, int cnt,
                            int* __restrict__ flags) {
    int i = blockIdx.x * blockDim.x + threadIdx.x;
    if (i < cnt) flags[tar[i]] = 1;
}

// ---------------------------------------------------------------------------
// Kernel: per-node projections y1[n] = x[n].W1, y2[n] = x[n].W2
// ---------------------------------------------------------------------------
__global__ void node_y_kernel(const float* __restrict__ x,
                              const float* __restrict__ W,   // [1, 3*DIM]
                              int n,
                              float* __restrict__ y1,
                              float* __restrict__ y2) {
    int warp = (blockIdx.x * blockDim.x + threadIdx.x) >> 5;
    int lane = threadIdx.x & 31;
    if (warp >= n) return;
    const float4* xr = (const float4*)(x + (long)warp * DIM);
    const float4* w1 = (const float4*)(W + DIM);
    const float4* w2 = (const float4*)(W + 2 * DIM);
    float s1 = 0.f, s2 = 0.f;
#pragma unroll
    for (int k = 0; k < 2; k++) {
        int i = lane * 2 + k;                  // 64 float4 per row
        float4 xv = xr[i];
        float4 a  = w1[i];
        float4 b  = w2[i];
        s1 += xv.x * a.x + xv.y * a.y + xv.z * a.z + xv.w * a.w;
        s2 += xv.x * b.x + xv.y * b.y + xv.z * b.z + xv.w * b.w;
    }
#pragma unroll
    for (int o = 16; o; o >>= 1) {
        s1 += __shfl_xor_sync(0xFFFFFFFFu, s1, o);
        s2 += __shfl_xor_sync(0xFFFFFFFFu, s2, o);
    }
    if (lane == 0) { y1[warp] = s1; y2[warp] = s2; }
}

// ---------------------------------------------------------------------------
// edge_dot: out[e] = xij.W0 + cn0 corrections (raw adj1 bits) + bias.
// Independent of pack -> runs CONCURRENTLY with pack via PDL.
// ---------------------------------------------------------------------------
__global__ void edge_dot_kernel(const float* __restrict__ x,
                                const int* __restrict__ tar,   // [2, E]
                                const float* __restrict__ W,   // [1, 3*DIM]
                                const float* __restrict__ bxs,
                                const unsigned* __restrict__ adj, // raw adj1
                                int n, int e_cnt,
                                const float* __restrict__ y1,
                                float* __restrict__ out) {
    cudaTriggerProgrammaticLaunchCompletion();
    int warp = (blockIdx.x * blockDim.x + threadIdx.x) >> 5;
    int lane = threadIdx.x & 31;
    if (warp >= e_cnt) return;

    int ti = tar[warp];
    int tj = tar[e_cnt + warp];

    // cn0 correction bits straight from the raw bool matrix (rare-taken).
    unsigned aii = 0, ajj = 0, aij = 0, aji = 0;
    if (lane == 0) {
        aii = adj[(long)ti * n + ti];
        aji = adj[(long)tj * n + ti];
        aij = adj[(long)ti * n + tj];
        ajj = adj[(long)tj * n + tj];
    }

    const float4* xi = (const float4*)(x + (long)ti * DIM);
    const float4* xj = (const float4*)(x + (long)tj * DIM);
    const float4* w0 = (const float4*)W;
    float s = 0.f;
#pragma unroll
    for (int k = 0; k < 2; k++) {
        int i = lane * 2 + k;
        float4 a  = xi[i];
        float4 b4 = xj[i];
        float4 w  = w0[i];
        s += a.x * b4.x * w.x + a.y * b4.y * w.y
           + a.z * b4.z * w.z + a.w * b4.w * w.w;
    }
#pragma unroll
    for (int o = 16; o; o >>= 1)
        s += __shfl_xor_sync(0xFFFFFFFFu, s, o);

    if (lane == 0) {
        float s0 = 0.f;
        if (ti == tj) {
            if (!aii) s0 = y1[ti];
        } else {
            if (aji && !aii) s0 += y1[ti];
            if (aij && !ajj) s0 += y1[tj];
        }
        out[warp] = s + s0 + bxs[0];
    }
}

// ---------------------------------------------------------------------------
// pack: adj1 (row-major N x N, 4-byte bool words) -> bitmasks.
// MLP=4 hot loop: each warp-iteration issues FOUR independent uint4 streaming
// loads (2 KB/warp in flight), then per group 4 ballots + one predicated
// store, with lanes 0..3 storing the four output uint4s in parallel (ballot
// results are warp-uniform). Groups 0..(4*nquads-1) are provably full for
// N=10000 (group 75 ends at col 9727) -> NO bounds checks in the hot loop.
// Tail groups handled per-warp on a cold path.
// Bit layout: word = group*4 + k; bit 'lane' = column group*128 + lane*4 + k.
// ---------------------------------------------------------------------------
__global__ void pack_adj_kernel(const unsigned int* __restrict__ adj,
                                const int* __restrict__ flags,
                                int n, int ngroups,
                                unsigned* __restrict__ bits) {
    int row = blockIdx.x;
    if (!flags[row]) return;
    int warp = threadIdx.x >> 5;
    int lane = threadIdx.x & 31;
    int nwarps = blockDim.x >> 5;

    const uint4* rowp4 = (const uint4*)(adj + (long)row * n);
    uint4* outp = (uint4*)(bits + (long)row * (ngroups * 4));

    int nquads = ngroups >> 2;                 // 19 quads (groups 0..75)
    for (int q = warp; q < nquads; q += nwarps) {
        int g0 = q * 4;
        // four independent streaming loads, front-batched
        uint4 v0 = __ldcs(&rowp4[(g0 + 0) * 32 + lane]);
        uint4 v1 = __ldcs(&rowp4[(g0 + 1) * 32 + lane]);
        uint4 v2 = __ldcs(&rowp4[(g0 + 2) * 32 + lane]);
        uint4 v3 = __ldcs(&rowp4[(g0 + 3) * 32 + lane]);

        unsigned a0 = __ballot_sync(0xFFFFFFFFu, v0.x != 0u);
        unsigned a1 = __ballot_sync(0xFFFFFFFFu, v0.y != 0u);
        unsigned a2 = __ballot_sync(0xFFFFFFFFu, v0.z != 0u);
        unsigned a3 = __ballot_sync(0xFFFFFFFFu, v0.w != 0u);
        unsigned b0 = __ballot_sync(0xFFFFFFFFu, v1.x != 0u);
        unsigned b1 = __ballot_sync(0xFFFFFFFFu, v1.y != 0u);
        unsigned b2 = __ballot_sync(0xFFFFFFFFu, v1.z != 0u);
        unsigned b3 = __ballot_sync(0xFFFFFFFFu, v1.w != 0u);
        unsigned c0 = __ballot_sync(0xFFFFFFFFu, v2.x != 0u);
        unsigned c1 = __ballot_sync(0xFFFFFFFFu, v2.y != 0u);
        unsigned c2 = __ballot_sync(0xFFFFFFFFu, v2.z != 0u);
        unsigned c3 = __ballot_sync(0xFFFFFFFFu, v2.w != 0u);
        unsigned d0 = __ballot_sync(0xFFFFFFFFu, v3.x != 0u);
        unsigned d1 = __ballot_sync(0xFFFFFFFFu, v3.y != 0u);
        unsigned d2 = __ballot_sync(0xFFFFFFFFu, v3.z != 0u);
        unsigned d3 = __ballot_sync(0xFFFFFFFFu, v3.w != 0u);

        // four parallel stores from lanes 0..3
        if (lane == 0)      outp[g0]     = make_uint4(a0, a1, a2, a3);
        else if (lane == 1) outp[g0 + 1] = make_uint4(b0, b1, b2, b3);
        else if (lane == 2) outp[g0 + 2] = make_uint4(c0, c1, c2, c3);
        else if (lane == 3) outp[g0 + 3] = make_uint4(d0, d1, d2, d3);
    }

    // tail: groups nquads*4 .. ngroups-1 (76,77,78 for N=10000), one warp each
    int tg = nquads * 4 + warp;
    if (tg < ngroups) {
        int col0 = tg * 128 + lane * 4;
        uint4 v = make_uint4(0u, 0u, 0u, 0u);
        if (col0 + 3 < n) {
            v = __ldcs(&rowp4[tg * 32 + lane]);
        } else if (col0 < n) {
            const unsigned* p = adj + (long)row * n + col0;
            v.x = p[0];
            if (col0 + 1 < n) v.y = p[1];
            if (col0 + 2 < n) v.z = p[2];
        }
        unsigned b0 = __ballot_sync(0xFFFFFFFFu, v.x != 0u);
        unsigned b1 = __ballot_sync(0xFFFFFFFFu, v.y != 0u);
        unsigned b2 = __ballot_sync(0xFFFFFFFFu, v.z != 0u);
        unsigned b3 = __ballot_sync(0xFFFFFFFFu, v.w != 0u);
        if (lane == 0)
            outp[tg] = make_uint4(b0, b1, b2, b3);
    }
}

// ---------------------------------------------------------------------------
// edge_cn: out[e] += sum_{n in cn1(e)} y2[n].  Needs pack complete.
// Bits rows live in L2 (12.6 MB). One warp per edge, uint4 per 128-col group.
// ---------------------------------------------------------------------------
__global__ void edge_cn_kernel(const int* __restrict__ tar,   // [2, E]
                               int e_cnt, int ngroups,
                               const unsigned* __restrict__ bits,
                               const float* __restrict__ y2,
                               float* __restrict__ out) {
    int warp = (blockIdx.x * blockDim.x + threadIdx.x) >> 5;
    int lane = threadIdx.x & 31;
    if (warp >= e_cnt) return;

    int ti = tar[warp];
    int tj = tar[e_cnt + warp];
    int wpg = ngroups * 4;

    const uint4* A = (const uint4*)(bits + (long)ti * wpg);
    const uint4* B = (const uint4*)(bits + (long)tj * wpg);

    float s = 0.f;
    for (int g = lane; g < ngroups; g += 32) {
        uint4 a = A[g];
        uint4 b = B[g];
        unsigned m0 = a.x & b.x, m1 = a.y & b.y;
        unsigned m2 = a.z & b.z, m3 = a.w & b.w;
        int base = g * 128;
        while (m0) { int bb = __ffs(m0) - 1; m0 &= m0 - 1; s += y2[base + bb * 4 + 0]; }
        while (m1) { int bb = __ffs(m1) - 1; m1 &= m1 - 1; s += y2[base + bb * 4 + 1]; }
        while (m2) { int bb = __ffs(m2) - 1; m2 &= m2 - 1; s += y2[base + bb * 4 + 2]; }
        while (m3) { int bb = __ffs(m3) - 1; m3 &= m3 - 1; s += y2[base + bb * 4 + 3]; }
    }
#pragma unroll
    for (int o = 16; o; o >>= 1)
        s += __shfl_xor_sync(0xFFFFFFFFu, s, o);

    if (lane == 0 && s != 0.f)
        out[warp] += s;
}

// ---------------------------------------------------------------------------
// Launch
// Inputs (metadata order): x[N*D] f32, adj01[N*N], adj1[N*N], tar_ei[2*E] i32,
//                          Wxs[1*3D] f32, bxs[1] f32, NCN_mode i32 (==0)
// Output: [E, 1] f32
// Stream order: flags, node_y, edge_dot(trigger), pack(PSS=1, overlapped),
//               edge_cn (waits pack; pack >> edge_dot so ordering holds).
// ---------------------------------------------------------------------------
extern "C" void kernel_launch(void* const* d_in, const int* in_sizes, int n_in,
                              void* d_out, int out_size) {
    const float*        x    = (const float*)d_in[0];
    const unsigned int* adj1 = (const unsigned int*)d_in[2];  // bool as 4-byte words
    const int*          tar  = (const int*)d_in[3];
    const float*        Wxs  = (const float*)d_in[4];
    const float*        bxs  = (const float*)d_in[5];
    float*              out  = (float*)d_out;

    const int N = in_sizes[0] / DIM;            // 10000
    const int E = in_sizes[3] / 2;              // 8192
    const int NGRP = (N + 127) / 128;           // 79

    unsigned* bits;
    float *y1, *y2;
    int* flags;
    cudaGetSymbolAddress((void**)&bits, g_bits32);
    cudaGetSymbolAddress((void**)&y1, g_y1);
    cudaGetSymbolAddress((void**)&y2, g_y2);
    cudaGetSymbolAddress((void**)&flags, g_flags);

    // Flags: zero then scatter-mark rows referenced by tar_ei
    cudaMemsetAsync(flags, 0, (size_t)N * sizeof(int));
    flag_kernel<<<(2 * E + 255) / 256, 256>>>(tar, 2 * E, flags);

    // Per-node projections (needed by edge_dot's cn0 corrections)
    node_y_kernel<<<(N + 7) / 8, 256>>>(x, Wxs, N, y1, y2);

    // edge_dot: single-wave grid (1024 blocks), PDL trigger at block start
    edge_dot_kernel<<<(E + 7) / 8, 256>>>(x, tar, Wxs, bxs, adj1, N, E, y1, out);

    // pack: programmatic stream serialization -> overlaps edge_dot.
    {
        cudaLaunchConfig_t cfg = {};
        cfg.gridDim  = dim3((unsigned)N);
        cfg.blockDim = dim3(256);
        cudaLaunchAttribute attr[1];
        attr[0].id = cudaLaunchAttributeProgrammaticStreamSerialization;
        attr[0].val.programmaticStreamSerializationAllowed = 1;
        cfg.attrs = attr;
        cfg.numAttrs = 1;
        cudaLaunchKernelEx(&cfg, pack_adj_kernel, adj1,
                           (const int*)flags, N, NGRP, (unsigned*)bits);
    }

    // edge_cn: plain launch -> waits for pack completion
    edge_cn_kernel<<<(E + 7) / 8, 256>>>(tar, E, NGRP, bits, y2, out);

    (void)n_in; (void)out_size;
}